// round 7
// baseline (speedup 1.0000x reference)
#include <cuda_runtime.h>
#include <math.h>

// ---------------- problem constants ----------------
#define BS    64
#define NSEG  3
#define SLEN  256
#define B3    192
#define TT    768
#define EDIM  300
#define HDIM  512
#define G3    1536
#define NNODE 18
#define NFEAT 600
#define NHID  600
#define NOUT  1024
#define BN    1152

// persistent GRU geometry
#define NKG   16
#define NBG   9
#define NSLOT 24

// output layout (floats)
#define OUT_RFTS 0UL
#define OUT_EMBS 25165824UL
#define OUT_MSKS 39911424UL
#define OUT_SG   39960576UL
#define OUT_HIDS 41140224UL

typedef unsigned long long u64;

// ---------------- f32x2 helpers ----------------
__device__ __forceinline__ u64 pk2(float x, float y) {
    u64 r; asm("mov.b64 %0, {%1, %2};" : "=l"(r) : "f"(x), "f"(y)); return r;
}
__device__ __forceinline__ void f2(u64& a, u64 b, u64 c) {
    asm("fma.rn.f32x2 %0, %1, %2, %0;" : "+l"(a) : "l"(b), "l"(c));
}
__device__ __forceinline__ float2 up2(u64 v) {
    float2 f; asm("mov.b64 {%0, %1}, %2;" : "=f"(f.x), "=f"(f.y) : "l"(v)); return f;
}
__device__ __forceinline__ float red2(u64 a, u64 b) {
    float2 x = up2(a), y = up2(b);
    return (x.x + x.y) + (y.x + y.y);
}

// ---------------- scratch ----------------
__device__ float g_xi[(size_t)B3 * SLEN * G3];
__device__ float g_h[2][B3 * HDIM];
__device__ float g_wihT[EDIM * G3];
__device__ float g_t1[BN * NHID];
__device__ float g_h1[BN * NHID];
__device__ float g_t2[BN * NOUT];
__device__ int   g_len[B3];
__device__ int   g_off[B3];
__device__ int   g_tlen[BS];
__device__ int   g_gmax[NBG];
__device__ int   g_bar_cnt[NBG];
__device__ int   g_bar_gen[NBG];
__device__ int   g_bmap[NBG * NSLOT];

// ---------------- prep ----------------
__global__ void prep_kernel(const int* __restrict__ lens) {
    __shared__ int s_len[B3];
    __shared__ int hist[257];
    __shared__ int sorted_b[B3];
    int tid = threadIdx.x;

    for (int i = tid; i < 257; i += 256) hist[i] = 0;
    for (int i = tid; i < NBG * NSLOT; i += 256) g_bmap[i] = -1;
    if (tid < NBG) { g_bar_cnt[tid] = 0; g_bar_gen[tid] = 0; g_gmax[tid] = 0; }
    __syncthreads();

    if (tid < B3) {
        int l = lens[tid];
        s_len[tid] = l;
        g_len[tid] = l;
        atomicAdd(&hist[l], 1);
        int bb = tid / NSEG, s = tid % NSEG;
        int off = 0;
        for (int s2 = 0; s2 < s; s2++) off += lens[bb * NSEG + s2];
        g_off[tid] = off;
        if (s == 0)
            g_tlen[bb] = lens[bb*NSEG] + lens[bb*NSEG+1] + lens[bb*NSEG+2];
    }
    __syncthreads();
    if (tid == 0) {
        int acc = 0;
        for (int v = 1; v <= 256; v++) { int c = hist[v]; hist[v] = acc; acc += c; }
    }
    __syncthreads();
    if (tid < B3) {
        int pos = atomicAdd(&hist[s_len[tid]], 1);
        sorted_b[B3 - 1 - pos] = tid;
    }
    __syncthreads();
    if (tid < B3) {
        int i = tid;
        int b = sorted_b[i];
        int p = i % (2 * NBG);
        int g = (p < NBG) ? p : (2 * NBG - 1 - p);
        int slot = 2 * (i / (2 * NBG)) + ((p >= NBG) ? 1 : 0);
        g_bmap[g * NSLOT + slot] = b;
        atomicMax(&g_gmax[g], s_len[b]);
    }
}

__global__ void zero_h_kernel() {
    int i = blockIdx.x * blockDim.x + threadIdx.x;
    if (i < B3 * HDIM) g_h[0][i] = 0.f;
}

__global__ void transpose_wih_kernel(const float* __restrict__ w_ih) {
    for (int idx = blockIdx.x * blockDim.x + threadIdx.x;
         idx < EDIM * G3; idx += gridDim.x * blockDim.x) {
        int e = idx / G3, g = idx % G3;
        g_wihT[idx] = w_ih[g * EDIM + e];
    }
}

// ---------------- xi GEMM: 128x64 tile, 8x4 microtile, FFMA2 ----------------
#define XBM 128
#define XBN 64
#define XBK 16

__global__ __launch_bounds__(256, 2)
void xi_gemm_kernel(const int* __restrict__ inds, const float* __restrict__ emb,
                    const float* __restrict__ b_ih) {
    int tr = blockIdx.y * XBM;
    int n0 = blockIdx.x * XBN;
    int b3 = tr >> 8;
    int t0 = tr & 255;
    if (t0 >= g_len[b3]) return;

    __shared__ float As[XBK * XBM];
    __shared__ float Bs[XBK * XBN];
    __shared__ int   toksh[XBM];

    int tid = threadIdx.x;
    int tx = tid & 15, ty = tid >> 4;
    if (tid < XBM) toksh[tid] = inds[tr + tid];
    __syncthreads();

    // acc[p][j]: row-pair p (rows 2p,2p+1 within the 8-row microtile), col j
    u64 acc[4][4];
#pragma unroll
    for (int p = 0; p < 4; p++)
#pragma unroll
        for (int j = 0; j < 4; j++) acc[p][j] = 0ull;

    const int rr = tid >> 2;
    const int e4 = (tid & 3) * 4;
    const int be = tid >> 4;
    const int bn = (tid & 15) * 4;

    for (int e0 = 0; e0 < EDIM; e0 += XBK) {
#pragma unroll
        for (int i = 0; i < 2; i++) {
            int row = rr + i * 64;
            int e = e0 + e4;
            float4 v = make_float4(0.f, 0.f, 0.f, 0.f);
            const float* ep = emb + (size_t)toksh[row] * EDIM;
            if (e + 3 < EDIM) v = *(const float4*)(ep + e);
            else {
                if (e     < EDIM) v.x = ep[e];
                if (e + 1 < EDIM) v.y = ep[e + 1];
                if (e + 2 < EDIM) v.z = ep[e + 2];
                if (e + 3 < EDIM) v.w = ep[e + 3];
            }
            As[(e4 + 0) * XBM + row] = v.x;
            As[(e4 + 1) * XBM + row] = v.y;
            As[(e4 + 2) * XBM + row] = v.z;
            As[(e4 + 3) * XBM + row] = v.w;
        }
        {
            float4 v = make_float4(0.f, 0.f, 0.f, 0.f);
            if (e0 + be < EDIM)
                v = *(const float4*)&g_wihT[(size_t)(e0 + be) * G3 + n0 + bn];
            *(float4*)&Bs[be * XBN + bn] = v;
        }
        __syncthreads();
#pragma unroll
        for (int e = 0; e < XBK; e++) {
            ulonglong2 a01 = *(const ulonglong2*)&As[e * XBM + ty * 8];      // rows 0-3 as 2 pairs
            ulonglong2 a23 = *(const ulonglong2*)&As[e * XBM + ty * 8 + 4];  // rows 4-7
            float4 b = *(const float4*)&Bs[e * XBN + tx * 4];
            u64 bx = pk2(b.x, b.x), by = pk2(b.y, b.y);
            u64 bz = pk2(b.z, b.z), bw = pk2(b.w, b.w);
            f2(acc[0][0], a01.x, bx); f2(acc[0][1], a01.x, by); f2(acc[0][2], a01.x, bz); f2(acc[0][3], a01.x, bw);
            f2(acc[1][0], a01.y, bx); f2(acc[1][1], a01.y, by); f2(acc[1][2], a01.y, bz); f2(acc[1][3], a01.y, bw);
            f2(acc[2][0], a23.x, bx); f2(acc[2][1], a23.x, by); f2(acc[2][2], a23.x, bz); f2(acc[2][3], a23.x, bw);
            f2(acc[3][0], a23.y, bx); f2(acc[3][1], a23.y, by); f2(acc[3][2], a23.y, bz); f2(acc[3][3], a23.y, bw);
        }
        __syncthreads();
    }
    float4 bias = *(const float4*)&b_ih[n0 + tx * 4];
#pragma unroll
    for (int p = 0; p < 4; p++) {
        float2 c0 = up2(acc[p][0]), c1 = up2(acc[p][1]);
        float2 c2 = up2(acc[p][2]), c3 = up2(acc[p][3]);
        int rg = tr + ty * 8 + 2 * p;
        float4 vlo = make_float4(c0.x + bias.x, c1.x + bias.y, c2.x + bias.z, c3.x + bias.w);
        float4 vhi = make_float4(c0.y + bias.x, c1.y + bias.y, c2.y + bias.z, c3.y + bias.w);
        *(float4*)&g_xi[(size_t)rg * G3 + n0 + tx * 4] = vlo;
        *(float4*)&g_xi[(size_t)(rg + 1) * G3 + n0 + tx * 4] = vhi;
    }
}

// ---------------- persistent GRU (FFMA2 inner loops) ----------------
__global__ __launch_bounds__(256, 1)
void gru_persist_kernel(const float* __restrict__ w_hh, const float* __restrict__ b_hh,
                        float* __restrict__ out) {
    extern __shared__ float4 W4[];
    const int kg = blockIdx.x, bg = blockIdx.y;
    const int tid = threadIdx.x, lane = tid & 31, w = tid >> 5;

    for (int i = tid; i < 128 * 3 * 32; i += 256) {
        int lc = i & 31, gj = i >> 5;
        int g = gj % 3, j = gj / 3;
        W4[i] = *(const float4*)&w_hh[(size_t)(g * HDIM + kg * 32 + lc) * HDIM + 4 * j];
    }

    const int k = kg * 32 + lane;
    const float bh_r = b_hh[k], bh_z = b_hh[HDIM + k], bh_n = b_hh[2 * HDIM + k];
    __syncthreads();

    const int gmax = g_gmax[bg];

    int bj[3], len_[3], row_[3];
#pragma unroll
    for (int j = 0; j < 3; j++) {
        int b = g_bmap[bg * NSLOT + w * 3 + j];
        bj[j] = b;
        len_[j] = (b >= 0) ? g_len[b] : 0;
        row_[j] = (b >= 0) ? (b / NSEG) * TT + g_off[b] : 0;
    }

    for (int t = 0; t < gmax; t++) {
        const float* __restrict__ hc = g_h[t & 1];
        float* __restrict__ hn = g_h[(t + 1) & 1];
        const bool a0 = t < len_[0], a1 = t < len_[1], a2 = t < len_[2];
        const int nact = (int)a0 + (int)a1 + (int)a2;

        float AR[3], AZ[3], AN[3];
        AR[0]=AR[1]=AR[2]=0.f; AZ[0]=AZ[1]=AZ[2]=0.f; AN[0]=AN[1]=AN[2]=0.f;

        if (nact == 3) {
            const float4* h0p = (const float4*)(hc + (size_t)bj[0] * HDIM);
            const float4* h1p = (const float4*)(hc + (size_t)bj[1] * HDIM);
            const float4* h2p = (const float4*)(hc + (size_t)bj[2] * HDIM);
            float4 H0[4], H1[4], H2[4];
#pragma unroll
            for (int r = 0; r < 4; r++) {
                H0[r] = h0p[r * 32 + lane];
                H1[r] = h1p[r * 32 + lane];
                H2[r] = h2p[r * 32 + lane];
            }
            u64 c0r0=0,c0r1=0,c0z0=0,c0z1=0,c0n0=0,c0n1=0;
            u64 c1r0=0,c1r1=0,c1z0=0,c1z1=0,c1n0=0,c1n1=0;
            u64 c2r0=0,c2r1=0,c2z0=0,c2z1=0,c2n0=0,c2n1=0;
#pragma unroll
            for (int r = 0; r < 4; r++) {
                const ulonglong2* Wr = (const ulonglong2*)(W4 + r * 3072);
                float4 h0 = H0[r], h1 = H1[r], h2 = H2[r];
#pragma unroll 4
                for (int s = 0; s < 32; s++) {
                    ulonglong2 w0 = Wr[s * 96 + lane];
                    ulonglong2 w1 = Wr[s * 96 + 32 + lane];
                    ulonglong2 w2 = Wr[s * 96 + 64 + lane];
                    float hx, hy, hz, hw;
                    u64 hA, hB;
                    hx = __shfl_sync(0xffffffffu, h0.x, s);
                    hy = __shfl_sync(0xffffffffu, h0.y, s);
                    hz = __shfl_sync(0xffffffffu, h0.z, s);
                    hw = __shfl_sync(0xffffffffu, h0.w, s);
                    hA = pk2(hx, hy); hB = pk2(hz, hw);
                    f2(c0r0, w0.x, hA); f2(c0r1, w0.y, hB);
                    f2(c0z0, w1.x, hA); f2(c0z1, w1.y, hB);
                    f2(c0n0, w2.x, hA); f2(c0n1, w2.y, hB);
                    hx = __shfl_sync(0xffffffffu, h1.x, s);
                    hy = __shfl_sync(0xffffffffu, h1.y, s);
                    hz = __shfl_sync(0xffffffffu, h1.z, s);
                    hw = __shfl_sync(0xffffffffu, h1.w, s);
                    hA = pk2(hx, hy); hB = pk2(hz, hw);
                    f2(c1r0, w0.x, hA); f2(c1r1, w0.y, hB);
                    f2(c1z0, w1.x, hA); f2(c1z1, w1.y, hB);
                    f2(c1n0, w2.x, hA); f2(c1n1, w2.y, hB);
                    hx = __shfl_sync(0xffffffffu, h2.x, s);
                    hy = __shfl_sync(0xffffffffu, h2.y, s);
                    hz = __shfl_sync(0xffffffffu, h2.z, s);
                    hw = __shfl_sync(0xffffffffu, h2.w, s);
                    hA = pk2(hx, hy); hB = pk2(hz, hw);
                    f2(c2r0, w0.x, hA); f2(c2r1, w0.y, hB);
                    f2(c2z0, w1.x, hA); f2(c2z1, w1.y, hB);
                    f2(c2n0, w2.x, hA); f2(c2n1, w2.y, hB);
                }
            }
            AR[0]=red2(c0r0,c0r1); AZ[0]=red2(c0z0,c0z1); AN[0]=red2(c0n0,c0n1);
            AR[1]=red2(c1r0,c1r1); AZ[1]=red2(c1z0,c1z1); AN[1]=red2(c1n0,c1n1);
            AR[2]=red2(c2r0,c2r1); AZ[2]=red2(c2z0,c2z1); AN[2]=red2(c2n0,c2n1);
        } else if (nact > 0) {
#pragma unroll
            for (int j = 0; j < 3; j++) {
                bool aj = (j == 0) ? a0 : ((j == 1) ? a1 : a2);
                if (!aj) continue;
                const float4* hp = (const float4*)(hc + (size_t)bj[j] * HDIM);
                float4 Hr[4];
#pragma unroll
                for (int r = 0; r < 4; r++) Hr[r] = hp[r * 32 + lane];
                u64 cr0=0,cr1=0,cz0=0,cz1=0,cn0=0,cn1=0;
#pragma unroll
                for (int r = 0; r < 4; r++) {
                    const ulonglong2* Wr = (const ulonglong2*)(W4 + r * 3072);
                    float4 h0 = Hr[r];
#pragma unroll 4
                    for (int s = 0; s < 32; s++) {
                        float hx = __shfl_sync(0xffffffffu, h0.x, s);
                        float hy = __shfl_sync(0xffffffffu, h0.y, s);
                        float hz = __shfl_sync(0xffffffffu, h0.z, s);
                        float hw = __shfl_sync(0xffffffffu, h0.w, s);
                        u64 hA = pk2(hx, hy), hB = pk2(hz, hw);
                        ulonglong2 w0 = Wr[s * 96 + lane];
                        ulonglong2 w1 = Wr[s * 96 + 32 + lane];
                        ulonglong2 w2 = Wr[s * 96 + 64 + lane];
                        f2(cr0, w0.x, hA); f2(cr1, w0.y, hB);
                        f2(cz0, w1.x, hA); f2(cz1, w1.y, hB);
                        f2(cn0, w2.x, hA); f2(cn1, w2.y, hB);
                    }
                }
                AR[j]=red2(cr0,cr1); AZ[j]=red2(cz0,cz1); AN[j]=red2(cn0,cn1);
            }
        }

#pragma unroll
        for (int j = 0; j < 3; j++) {
            int b = bj[j];
            if (b < 0) continue;
            float hold = hc[(size_t)b * HDIM + k];
            float hv = hold;
            if (t < len_[j]) {
                const float* xi = g_xi + ((size_t)b * SLEN + t) * G3;
                float rr = 1.f / (1.f + expf(-(xi[k] + AR[j] + bh_r)));
                float zz = 1.f / (1.f + expf(-(xi[HDIM + k] + AZ[j] + bh_z)));
                float nn = tanhf(xi[2 * HDIM + k] + rr * (AN[j] + bh_n));
                hv = (1.f - zz) * nn + zz * hold;
                out[OUT_RFTS + ((size_t)(row_[j] + t)) * HDIM + k] = hv;
            }
            hn[(size_t)b * HDIM + k] = hv;
        }

        __threadfence();
        __syncthreads();
        if (tid == 0) {
            int a = atomicAdd(&g_bar_cnt[bg], 1);
            if (a == NKG - 1) {
                atomicExch(&g_bar_cnt[bg], 0);
                __threadfence();
                atomicExch(&g_bar_gen[bg], t + 1);
            } else {
                while (atomicAdd(&g_bar_gen[bg], 0) <= t) { }
                __threadfence();
            }
        }
        __syncthreads();
    }

    const float* hf = g_h[gmax & 1];
#pragma unroll
    for (int j = 0; j < 3; j++) {
        if (bj[j] >= 0)
            out[OUT_HIDS + (size_t)bj[j] * HDIM + k] = hf[(size_t)bj[j] * HDIM + k];
    }
}

// ---------------- packing & masks ----------------
__global__ void msks_kernel(float* __restrict__ out) {
    int b = blockIdx.x, t = threadIdx.x;
    out[OUT_MSKS + (size_t)b * TT + t] = (t < g_tlen[b]) ? 1.f : 0.f;
}

__global__ void pack_emb_kernel(const int* __restrict__ inds,
                                const float* __restrict__ emb,
                                float* __restrict__ out) {
    int t = blockIdx.x, b3 = blockIdx.y;
    if (t >= g_len[b3]) return;
    int tok = inds[b3 * SLEN + t];
    size_t row = (size_t)(b3 / 3) * TT + g_off[b3] + t;
    for (int e = threadIdx.x; e < EDIM; e += blockDim.x)
        out[OUT_EMBS + row * EDIM + e] = emb[(size_t)tok * EDIM + e];
}

// ---------------- GCN GEMM (FFMA2) ----------------
__global__ __launch_bounds__(256)
void gemm64_kernel(const float* __restrict__ A, const float* __restrict__ B,
                   float* __restrict__ C, int M, int N, int K) {
    const int BK = 8;
    int m0 = blockIdx.y * 64, n0 = blockIdx.x * 64;
    __shared__ float As[BK * 64];
    __shared__ float Bs[BK * 64];
    int tid = threadIdx.x;
    int tx = tid & 15, ty = tid >> 4;

    u64 acc[2][4];
#pragma unroll
    for (int p = 0; p < 2; p++)
#pragma unroll
        for (int j = 0; j < 4; j++) acc[p][j] = 0ull;

    for (int k0 = 0; k0 < K; k0 += BK) {
#pragma unroll
        for (int i = 0; i < 2; i++) {
            int idx = tid + i * 256;
            int r = idx / BK, e = idx % BK;
            float v = 0.f;
            if (m0 + r < M) v = A[(size_t)(m0 + r) * K + k0 + e];
            As[e * 64 + r] = v;
        }
#pragma unroll
        for (int i = 0; i < 2; i++) {
            int idx = tid + i * 256;
            int e = idx >> 6, n = idx & 63;
            float v = 0.f;
            if (n0 + n < N) v = B[(size_t)(k0 + e) * N + n0 + n];
            Bs[e * 64 + n] = v;
        }
        __syncthreads();
#pragma unroll
        for (int e = 0; e < BK; e++) {
            ulonglong2 a = *(const ulonglong2*)&As[e * 64 + ty * 4];
            float4 b = *(const float4*)&Bs[e * 64 + tx * 4];
            u64 bx = pk2(b.x, b.x), by = pk2(b.y, b.y);
            u64 bz = pk2(b.z, b.z), bw = pk2(b.w, b.w);
            f2(acc[0][0], a.x, bx); f2(acc[0][1], a.x, by); f2(acc[0][2], a.x, bz); f2(acc[0][3], a.x, bw);
            f2(acc[1][0], a.y, bx); f2(acc[1][1], a.y, by); f2(acc[1][2], a.y, bz); f2(acc[1][3], a.y, bw);
        }
        __syncthreads();
    }
#pragma unroll
    for (int p = 0; p < 2; p++) {
        float2 c0 = up2(acc[p][0]), c1 = up2(acc[p][1]);
        float2 c2 = up2(acc[p][2]), c3 = up2(acc[p][3]);
        int rg = m0 + ty * 4 + 2 * p;
#pragma unroll
        for (int h = 0; h < 2; h++) {
            int row = rg + h;
            if (row >= M) continue;
            float v0 = h ? c0.y : c0.x, v1 = h ? c1.y : c1.x;
            float v2 = h ? c2.y : c2.x, v3 = h ? c3.y : c3.x;
            int cg = n0 + tx * 4;
            if (cg     < N) C[(size_t)row * N + cg]     = v0;
            if (cg + 1 < N) C[(size_t)row * N + cg + 1] = v1;
            if (cg + 2 < N) C[(size_t)row * N + cg + 2] = v2;
            if (cg + 3 < N) C[(size_t)row * N + cg + 3] = v3;
        }
    }
}

__global__ void adjmul_kernel(const float* __restrict__ adj, const float* __restrict__ X,
                              const float* __restrict__ bias, float* __restrict__ Y,
                              int F, int relu) {
    int total = BS * NNODE * F;
    for (int idx = blockIdx.x * blockDim.x + threadIdx.x; idx < total;
         idx += gridDim.x * blockDim.x) {
        int f = idx % F;
        int n = (idx / F) % NNODE;
        int b = idx / (F * NNODE);
        const float* Xb = X + (size_t)(b * NNODE) * F;
        const float* ad = adj + (size_t)(b * NNODE + n) * NNODE;
        float acc = bias[f];
#pragma unroll
        for (int m = 0; m < NNODE; m++)
            acc = fmaf(ad[m], Xb[(size_t)m * F + f], acc);
        if (relu) acc = fmaxf(acc, 0.f);
        Y[idx] = acc;
    }
}

// ---------------- host ----------------
extern "C" void kernel_launch(void* const* d_in, const int* in_sizes, int n_in,
                              void* d_out, int out_size) {
    const int*   inds = (const int*)  d_in[0];
    const int*   lens = (const int*)  d_in[1];
    const float* emb  = (const float*)d_in[2];
    const float* w_ih = (const float*)d_in[3];
    const float* w_hh = (const float*)d_in[4];
    const float* b_ih = (const float*)d_in[5];
    const float* b_hh = (const float*)d_in[6];
    const float* sg_x = (const float*)d_in[7];
    const float* adj  = (const float*)d_in[8];
    const float* gw1  = (const float*)d_in[9];
    const float* gb1  = (const float*)d_in[10];
    const float* gw2  = (const float*)d_in[11];
    const float* gb2  = (const float*)d_in[12];
    float* out = (float*)d_out;

    const int WSMEM = 128 * 3 * 32 * 16;
    cudaFuncSetAttribute(gru_persist_kernel,
                         cudaFuncAttributeMaxDynamicSharedMemorySize, WSMEM);

    cudaMemsetAsync(d_out, 0, (size_t)out_size * sizeof(float), 0);
    zero_h_kernel<<<(B3 * HDIM + 511) / 512, 512>>>();
    prep_kernel<<<1, 256>>>(lens);
    transpose_wih_kernel<<<512, 256>>>(w_ih);

    xi_gemm_kernel<<<dim3(G3 / XBN, (B3 * SLEN) / XBM), 256>>>(inds, emb, b_ih);

    msks_kernel<<<BS, TT>>>(out);
    pack_emb_kernel<<<dim3(SLEN, B3), 64>>>(inds, emb, out);

    gru_persist_kernel<<<dim3(NKG, NBG), 256, WSMEM>>>(w_hh, b_hh, out);

    // GCN
    gemm64_kernel<<<dim3((NHID + 63) / 64, (BN + 63) / 64), 256>>>(sg_x, gw1, g_t1, BN, NHID, NFEAT);
    adjmul_kernel<<<1350, 512>>>(adj, g_t1, gb1, g_h1, NHID, 1);
    gemm64_kernel<<<dim3((NOUT + 63) / 64, (BN + 63) / 64), 256>>>(g_h1, gw2, g_t2, BN, NOUT, NHID);
    adjmul_kernel<<<2304, 512>>>(adj, g_t2, gb2, out + OUT_SG, NOUT, 0);
}

// round 8
// speedup vs baseline: 1.3150x; 1.3150x over previous
#include <cuda_runtime.h>
#include <math.h>
#include <stdint.h>

// ---------------- problem constants ----------------
#define BS    64
#define NSEG  3
#define SLEN  256
#define B3    192
#define TT    768
#define EDIM  300
#define HDIM  512
#define G3    1536
#define NNODE 18
#define NFEAT 600
#define NHID  600
#define NOUT  1024
#define BN    1152

// persistent GRU geometry
#define NKG   16          // k-groups (32 h-columns each)
#define NBG   9           // b-groups
#define NSLOT 24          // filled slots per group (M padded to 32)

// output layout (floats)
#define OUT_RFTS 0UL
#define OUT_EMBS 25165824UL
#define OUT_MSKS 39911424UL
#define OUT_SG   39960576UL
#define OUT_HIDS 41140224UL

// GRU smem layout (floats)
#define WPK_FLOATS 49152                  // 96 cols x 512 k, tf32 bits
#define A_OFF      WPK_FLOATS             // A chunk buffer [32][68]
#define A_STRIDE   68
#define GHS_OFF    (A_OFF + 32*A_STRIDE)  // gh dump [32][100]
#define GHS_STRIDE 100
#define BSH_OFF    (GHS_OFF + 32*GHS_STRIDE)
#define SMEM_FLOATS (BSH_OFF + 96)
#define GRU_SMEM_BYTES (SMEM_FLOATS * 4)  // 218496 B

// ---------------- scratch ----------------
__device__ float g_xi[(size_t)B3 * SLEN * G3];
__device__ float g_h[2][B3 * HDIM];
__device__ float g_wihT[EDIM * G3];
__device__ float g_t1[BN * NHID];
__device__ float g_h1[BN * NHID];
__device__ float g_t2[BN * NOUT];
__device__ int   g_len[B3];
__device__ int   g_off[B3];
__device__ int   g_tlen[BS];
__device__ int   g_gmax[NBG];
__device__ int   g_bar_cnt[NBG];
__device__ int   g_bar_gen[NBG];
__device__ int   g_bmap[NBG * NSLOT];

// ---------------- small helpers ----------------
__device__ __forceinline__ uint32_t tf32c(float x) {
    uint32_t u; asm("cvt.rna.tf32.f32 %0, %1;" : "=r"(u) : "f"(x)); return u;
}
__device__ __forceinline__ void mma8(float* d, uint32_t a0, uint32_t a1,
                                     uint32_t a2, uint32_t a3,
                                     uint32_t b0, uint32_t b1) {
    asm volatile(
        "mma.sync.aligned.m16n8k8.row.col.f32.tf32.tf32.f32 "
        "{%0,%1,%2,%3}, {%4,%5,%6,%7}, {%8,%9}, {%0,%1,%2,%3};"
        : "+f"(d[0]), "+f"(d[1]), "+f"(d[2]), "+f"(d[3])
        : "r"(a0), "r"(a1), "r"(a2), "r"(a3), "r"(b0), "r"(b1));
}

// ---------------- prep ----------------
__global__ void prep_kernel(const int* __restrict__ lens) {
    __shared__ int s_len[B3];
    __shared__ int hist[257];
    __shared__ int sorted_b[B3];
    int tid = threadIdx.x;

    for (int i = tid; i < 257; i += 256) hist[i] = 0;
    for (int i = tid; i < NBG * NSLOT; i += 256) g_bmap[i] = -1;
    if (tid < NBG) { g_bar_cnt[tid] = 0; g_bar_gen[tid] = 0; g_gmax[tid] = 0; }
    __syncthreads();

    if (tid < B3) {
        int l = lens[tid];
        s_len[tid] = l;
        g_len[tid] = l;
        atomicAdd(&hist[l], 1);
        int bb = tid / NSEG, s = tid % NSEG;
        int off = 0;
        for (int s2 = 0; s2 < s; s2++) off += lens[bb * NSEG + s2];
        g_off[tid] = off;
        if (s == 0)
            g_tlen[bb] = lens[bb*NSEG] + lens[bb*NSEG+1] + lens[bb*NSEG+2];
    }
    __syncthreads();
    if (tid == 0) {
        int acc = 0;
        for (int v = 1; v <= 256; v++) { int c = hist[v]; hist[v] = acc; acc += c; }
    }
    __syncthreads();
    if (tid < B3) {
        int pos = atomicAdd(&hist[s_len[tid]], 1);
        sorted_b[B3 - 1 - pos] = tid;
    }
    __syncthreads();
    if (tid < B3) {
        int i = tid;
        int b = sorted_b[i];
        int p = i % (2 * NBG);
        int g = (p < NBG) ? p : (2 * NBG - 1 - p);
        int slot = 2 * (i / (2 * NBG)) + ((p >= NBG) ? 1 : 0);
        g_bmap[g * NSLOT + slot] = b;
        atomicMax(&g_gmax[g], s_len[b]);
    }
}

__global__ void zero_h_kernel() {
    int i = blockIdx.x * blockDim.x + threadIdx.x;
    if (i < B3 * HDIM) g_h[0][i] = 0.f;
}

__global__ void transpose_wih_kernel(const float* __restrict__ w_ih) {
    for (int idx = blockIdx.x * blockDim.x + threadIdx.x;
         idx < EDIM * G3; idx += gridDim.x * blockDim.x) {
        int e = idx / G3, g = idx % G3;
        g_wihT[idx] = w_ih[g * EDIM + e];
    }
}

// ---------------- xi GEMM (R4 scalar version, 796us known-good) ----------------
#define XBM 128
#define XBN 64
#define XBK 16

__global__ __launch_bounds__(256, 2)
void xi_gemm_kernel(const int* __restrict__ inds, const float* __restrict__ emb,
                    const float* __restrict__ b_ih) {
    int tr = blockIdx.y * XBM;
    int n0 = blockIdx.x * XBN;
    int b3 = tr >> 8;
    int t0 = tr & 255;
    if (t0 >= g_len[b3]) return;

    __shared__ float As[XBK * XBM];
    __shared__ float Bs[XBK * XBN];
    __shared__ int   toksh[XBM];

    int tid = threadIdx.x;
    int tx = tid & 15, ty = tid >> 4;
    if (tid < XBM) toksh[tid] = inds[tr + tid];
    __syncthreads();

    float acc[8][4];
#pragma unroll
    for (int i = 0; i < 8; i++)
#pragma unroll
        for (int j = 0; j < 4; j++) acc[i][j] = 0.f;

    const int rr = tid >> 2;
    const int e4 = (tid & 3) * 4;
    const int be = tid >> 4;
    const int bn = (tid & 15) * 4;

    for (int e0 = 0; e0 < EDIM; e0 += XBK) {
#pragma unroll
        for (int i = 0; i < 2; i++) {
            int row = rr + i * 64;
            int e = e0 + e4;
            float4 v = make_float4(0.f, 0.f, 0.f, 0.f);
            const float* ep = emb + (size_t)toksh[row] * EDIM;
            if (e + 3 < EDIM) v = *(const float4*)(ep + e);
            else {
                if (e     < EDIM) v.x = ep[e];
                if (e + 1 < EDIM) v.y = ep[e + 1];
                if (e + 2 < EDIM) v.z = ep[e + 2];
                if (e + 3 < EDIM) v.w = ep[e + 3];
            }
            As[(e4 + 0) * XBM + row] = v.x;
            As[(e4 + 1) * XBM + row] = v.y;
            As[(e4 + 2) * XBM + row] = v.z;
            As[(e4 + 3) * XBM + row] = v.w;
        }
        {
            float4 v = make_float4(0.f, 0.f, 0.f, 0.f);
            if (e0 + be < EDIM)
                v = *(const float4*)&g_wihT[(size_t)(e0 + be) * G3 + n0 + bn];
            *(float4*)&Bs[be * XBN + bn] = v;
        }
        __syncthreads();
#pragma unroll
        for (int e = 0; e < XBK; e++) {
            float4 b = *(const float4*)&Bs[e * XBN + tx * 4];
            float4 a0 = *(const float4*)&As[e * XBM + ty * 8];
            float4 a1 = *(const float4*)&As[e * XBM + ty * 8 + 4];
            acc[0][0]=fmaf(a0.x,b.x,acc[0][0]); acc[0][1]=fmaf(a0.x,b.y,acc[0][1]); acc[0][2]=fmaf(a0.x,b.z,acc[0][2]); acc[0][3]=fmaf(a0.x,b.w,acc[0][3]);
            acc[1][0]=fmaf(a0.y,b.x,acc[1][0]); acc[1][1]=fmaf(a0.y,b.y,acc[1][1]); acc[1][2]=fmaf(a0.y,b.z,acc[1][2]); acc[1][3]=fmaf(a0.y,b.w,acc[1][3]);
            acc[2][0]=fmaf(a0.z,b.x,acc[2][0]); acc[2][1]=fmaf(a0.z,b.y,acc[2][1]); acc[2][2]=fmaf(a0.z,b.z,acc[2][2]); acc[2][3]=fmaf(a0.z,b.w,acc[2][3]);
            acc[3][0]=fmaf(a0.w,b.x,acc[3][0]); acc[3][1]=fmaf(a0.w,b.y,acc[3][1]); acc[3][2]=fmaf(a0.w,b.z,acc[3][2]); acc[3][3]=fmaf(a0.w,b.w,acc[3][3]);
            acc[4][0]=fmaf(a1.x,b.x,acc[4][0]); acc[4][1]=fmaf(a1.x,b.y,acc[4][1]); acc[4][2]=fmaf(a1.x,b.z,acc[4][2]); acc[4][3]=fmaf(a1.x,b.w,acc[4][3]);
            acc[5][0]=fmaf(a1.y,b.x,acc[5][0]); acc[5][1]=fmaf(a1.y,b.y,acc[5][1]); acc[5][2]=fmaf(a1.y,b.z,acc[5][2]); acc[5][3]=fmaf(a1.y,b.w,acc[5][3]);
            acc[6][0]=fmaf(a1.z,b.x,acc[6][0]); acc[6][1]=fmaf(a1.z,b.y,acc[6][1]); acc[6][2]=fmaf(a1.z,b.z,acc[6][2]); acc[6][3]=fmaf(a1.z,b.w,acc[6][3]);
            acc[7][0]=fmaf(a1.w,b.x,acc[7][0]); acc[7][1]=fmaf(a1.w,b.y,acc[7][1]); acc[7][2]=fmaf(a1.w,b.z,acc[7][2]); acc[7][3]=fmaf(a1.w,b.w,acc[7][3]);
        }
        __syncthreads();
    }
    float4 bias = *(const float4*)&b_ih[n0 + tx * 4];
#pragma unroll
    for (int i = 0; i < 8; i++) {
        int rg = tr + ty * 8 + i;
        float4 v = make_float4(acc[i][0] + bias.x, acc[i][1] + bias.y,
                               acc[i][2] + bias.z, acc[i][3] + bias.w);
        *(float4*)&g_xi[(size_t)rg * G3 + n0 + tx * 4] = v;
    }
}

// ---------------- persistent GRU: tf32 mma.sync ----------------
// CTA(kg, bg): gh[32 b][96 n] = h[32x512] @ W[96x512]^T, n = 3*kc + gate.
// Warps: wid = mi + 2*nj (mi in {0,1} M-tile of 16, nj in 0..3 covering kc 8nj..8nj+7, all gates).
__global__ __launch_bounds__(256, 1)
void gru_mma_kernel(const float* __restrict__ w_hh, const float* __restrict__ b_hh,
                    float* __restrict__ out) {
    extern __shared__ float S[];
    uint32_t* Wu  = (uint32_t*)S;                 // packed B-frags (tf32 bits)
    uint32_t* Au  = (uint32_t*)(S + A_OFF);       // A chunk [32][68] (tf32 bits)
    float*    ghs = S + GHS_OFF;                  // [32][100]
    float*    bsh = S + BSH_OFF;                  // [96]
    __shared__ int sb3[32];
    __shared__ int slen[32];
    __shared__ int srow[32];

    const int kg = blockIdx.x, bg = blockIdx.y;
    const int tid = threadIdx.x, lane = tid & 31, wid = tid >> 5;
    const int mi = wid & 1, nj = wid >> 1;

    if (tid < 32) {
        int b = (tid < NSLOT) ? g_bmap[bg * NSLOT + tid] : -1;
        sb3[tid] = b;
        slen[tid] = (b >= 0) ? g_len[b] : 0;
        srow[tid] = (b >= 0) ? ((b / NSEG) * TT + g_off[b]) : 0;
    }
    if (tid < 96) {
        int kc = tid / 3, g = tid - 3 * (tid / 3);
        bsh[tid] = b_hh[g * HDIM + kg * 32 + kc];
    }
    // Pack W into per-warp B-fragment order: pair p = ((nj*64+q)*3+t)*32+lane,
    // halves: b0 at 2p (k=8q+(l&3)), b1 at 2p+1 (k=8q+4+(l&3)); n = 24nj+8t+(l>>2).
    for (int i = tid; i < WPK_FLOATS; i += 256) {
        int p = i >> 1, half = i & 1;
        int l  = p & 31;
        int tq = p >> 5;                 // (nj*64+q)*3 + t
        int t  = tq % 3;
        int qn = tq / 3;                 // nj*64 + q
        int q  = qn & 63;
        int njj = qn >> 6;
        int e  = 8 * q + (l & 3) + 4 * half;
        int c  = 8 * t + (l >> 2);       // n - 24*nj
        int kc = 8 * njj + c / 3;
        int g  = c - 3 * (c / 3);
        float v = w_hh[(size_t)(g * HDIM + kg * 32 + kc) * HDIM + e];
        Wu[i] = tf32c(v);
    }
    __syncthreads();

    const int gmax = g_gmax[bg];
    const int srowS = tid >> 3;          // stage row 0..31
    const int soct  = tid & 7;           // stage e-octet
    const int g4 = lane >> 2, tg = lane & 3;

    for (int t = 0; t < gmax; t++) {
        const float* __restrict__ hc = g_h[t & 1];
        float* __restrict__ hn = g_h[(t + 1) & 1];

        float d0[4] = {0,0,0,0}, d1[4] = {0,0,0,0}, d2[4] = {0,0,0,0};

        // stage prefetch for chunk 0
        const int sbb = sb3[srowS];
        const bool sval = (sbb >= 0);
        const float* hrow = sval ? (hc + (size_t)sbb * HDIM) : hc;
        float4 pv0, pv1;
        if (sval) {
            const float4* hp = (const float4*)(hrow + soct * 8);
            pv0 = hp[0]; pv1 = hp[1];
        } else { pv0 = pv1 = make_float4(0.f,0.f,0.f,0.f); }

        for (int ch = 0; ch < 8; ch++) {
            __syncthreads();   // previous chunk's readers done
            {
                uint4 u0, u1;
                u0.x = tf32c(pv0.x); u0.y = tf32c(pv0.y); u0.z = tf32c(pv0.z); u0.w = tf32c(pv0.w);
                u1.x = tf32c(pv1.x); u1.y = tf32c(pv1.y); u1.z = tf32c(pv1.z); u1.w = tf32c(pv1.w);
                uint32_t* ap = Au + srowS * A_STRIDE + soct * 8;
                *(uint4*)ap = u0;
                *(uint4*)(ap + 4) = u1;
                if (ch < 7 && sval) {
                    const float4* hp = (const float4*)(hrow + (ch + 1) * 64 + soct * 8);
                    pv0 = hp[0]; pv1 = hp[1];
                }
            }
            __syncthreads();
#pragma unroll
            for (int ql = 0; ql < 8; ql++) {
                const uint32_t* ab = Au + (16 * mi + g4) * A_STRIDE + ql * 8 + tg;
                uint32_t a0 = ab[0];
                uint32_t a1 = ab[8 * A_STRIDE];
                uint32_t a2 = ab[4];
                uint32_t a3 = ab[8 * A_STRIDE + 4];
                int q = ch * 8 + ql;
                const uint2* wp = (const uint2*)Wu + ((nj * 64 + q) * 3) * 32 + lane;
                uint2 bf0 = wp[0];
                uint2 bf1 = wp[32];
                uint2 bf2 = wp[64];
                mma8(d0, a0, a1, a2, a3, bf0.x, bf0.y);
                mma8(d1, a0, a1, a2, a3, bf1.x, bf1.y);
                mma8(d2, a0, a1, a2, a3, bf2.x, bf2.y);
            }
        }

        // dump gh fragments to smem
        {
            int r0 = (16 * mi + g4) * GHS_STRIDE;
            int r1 = (16 * mi + 8 + g4) * GHS_STRIDE;
            int n0 = 24 * nj + 2 * tg;
            ghs[r0 + n0]      = d0[0]; ghs[r0 + n0 + 1]  = d0[1];
            ghs[r1 + n0]      = d0[2]; ghs[r1 + n0 + 1]  = d0[3];
            ghs[r0 + n0 + 8]  = d1[0]; ghs[r0 + n0 + 9]  = d1[1];
            ghs[r1 + n0 + 8]  = d1[2]; ghs[r1 + n0 + 9]  = d1[3];
            ghs[r0 + n0 + 16] = d2[0]; ghs[r0 + n0 + 17] = d2[1];
            ghs[r1 + n0 + 16] = d2[2]; ghs[r1 + n0 + 17] = d2[3];
        }
        __syncthreads();

        // epilogue: gates + carry, 32 slots x 32 kc = 1024 items
#pragma unroll
        for (int it = 0; it < 4; it++) {
            int item = tid + it * 256;
            int s = item >> 5, kc = item & 31;
            int b3 = sb3[s];
            if (b3 >= 0) {
                int kglob = kg * 32 + kc;
                float hold = hc[(size_t)b3 * HDIM + kglob];
                float hv = hold;
                if (t < slen[s]) {
                    float gr = ghs[s * GHS_STRIDE + 3 * kc + 0];
                    float gz = ghs[s * GHS_STRIDE + 3 * kc + 1];
                    float gn = ghs[s * GHS_STRIDE + 3 * kc + 2];
                    const float* xi = g_xi + ((size_t)b3 * SLEN + t) * G3;
                    float rr = 1.f / (1.f + expf(-(xi[kglob] + gr + bsh[3 * kc])));
                    float zz = 1.f / (1.f + expf(-(xi[HDIM + kglob] + gz + bsh[3 * kc + 1])));
                    float nn = tanhf(xi[2 * HDIM + kglob] + rr * (gn + bsh[3 * kc + 2]));
                    hv = (1.f - zz) * nn + zz * hold;
                    out[OUT_RFTS + (size_t)(srow[s] + t) * HDIM + kglob] = hv;
                }
                hn[(size_t)b3 * HDIM + kglob] = hv;
            }
        }

        // inter-CTA barrier among this bg's NKG CTAs
        __threadfence();
        __syncthreads();
        if (tid == 0) {
            int a = atomicAdd(&g_bar_cnt[bg], 1);
            if (a == NKG - 1) {
                atomicExch(&g_bar_cnt[bg], 0);
                __threadfence();
                atomicExch(&g_bar_gen[bg], t + 1);
            } else {
                while (atomicAdd(&g_bar_gen[bg], 0) <= t) { }
                __threadfence();
            }
        }
        __syncthreads();
    }

    // final hidden states (own slice)
    const float* hf = g_h[gmax & 1];
#pragma unroll
    for (int it = 0; it < 4; it++) {
        int item = tid + it * 256;
        int s = item >> 5, kc = item & 31;
        int b3 = sb3[s];
        if (b3 >= 0) {
            int kglob = kg * 32 + kc;
            out[OUT_HIDS + (size_t)b3 * HDIM + kglob] = hf[(size_t)b3 * HDIM + kglob];
        }
    }
}

// ---------------- packing & masks ----------------
__global__ void msks_kernel(float* __restrict__ out) {
    int b = blockIdx.x, t = threadIdx.x;
    out[OUT_MSKS + (size_t)b * TT + t] = (t < g_tlen[b]) ? 1.f : 0.f;
}

__global__ void pack_emb_kernel(const int* __restrict__ inds,
                                const float* __restrict__ emb,
                                float* __restrict__ out) {
    int t = blockIdx.x, b3 = blockIdx.y;
    if (t >= g_len[b3]) return;
    int tok = inds[b3 * SLEN + t];
    size_t row = (size_t)(b3 / 3) * TT + g_off[b3] + t;
    for (int e = threadIdx.x; e < EDIM; e += blockDim.x)
        out[OUT_EMBS + row * EDIM + e] = emb[(size_t)tok * EDIM + e];
}

// ---------------- GCN GEMM (scalar) ----------------
__global__ __launch_bounds__(256)
void gemm64_kernel(const float* __restrict__ A, const float* __restrict__ B,
                   float* __restrict__ C, int M, int N, int K) {
    const int BK = 8;
    int m0 = blockIdx.y * 64, n0 = blockIdx.x * 64;
    __shared__ float As[BK * 64];
    __shared__ float Bs[BK * 64];
    int tid = threadIdx.x;
    int tx = tid & 15, ty = tid >> 4;

    float acc[4][4];
#pragma unroll
    for (int i = 0; i < 4; i++)
#pragma unroll
        for (int j = 0; j < 4; j++) acc[i][j] = 0.f;

    for (int k0 = 0; k0 < K; k0 += BK) {
#pragma unroll
        for (int i = 0; i < 2; i++) {
            int idx = tid + i * 256;
            int r = idx / BK, e = idx % BK;
            float v = 0.f;
            if (m0 + r < M) v = A[(size_t)(m0 + r) * K + k0 + e];
            As[e * 64 + r] = v;
        }
#pragma unroll
        for (int i = 0; i < 2; i++) {
            int idx = tid + i * 256;
            int e = idx >> 6, n = idx & 63;
            float v = 0.f;
            if (n0 + n < N) v = B[(size_t)(k0 + e) * N + n0 + n];
            Bs[e * 64 + n] = v;
        }
        __syncthreads();
#pragma unroll
        for (int e = 0; e < BK; e++) {
            float4 a = *(const float4*)&As[e * 64 + ty * 4];
            float4 b = *(const float4*)&Bs[e * 64 + tx * 4];
            acc[0][0] = fmaf(a.x, b.x, acc[0][0]); acc[0][1] = fmaf(a.x, b.y, acc[0][1]);
            acc[0][2] = fmaf(a.x, b.z, acc[0][2]); acc[0][3] = fmaf(a.x, b.w, acc[0][3]);
            acc[1][0] = fmaf(a.y, b.x, acc[1][0]); acc[1][1] = fmaf(a.y, b.y, acc[1][1]);
            acc[1][2] = fmaf(a.y, b.z, acc[1][2]); acc[1][3] = fmaf(a.y, b.w, acc[1][3]);
            acc[2][0] = fmaf(a.z, b.x, acc[2][0]); acc[2][1] = fmaf(a.z, b.y, acc[2][1]);
            acc[2][2] = fmaf(a.z, b.z, acc[2][2]); acc[2][3] = fmaf(a.z, b.w, acc[2][3]);
            acc[3][0] = fmaf(a.w, b.x, acc[3][0]); acc[3][1] = fmaf(a.w, b.y, acc[3][1]);
            acc[3][2] = fmaf(a.w, b.z, acc[3][2]); acc[3][3] = fmaf(a.w, b.w, acc[3][3]);
        }
        __syncthreads();
    }
#pragma unroll
    for (int i = 0; i < 4; i++) {
        int rg = m0 + ty * 4 + i;
        if (rg >= M) continue;
#pragma unroll
        for (int j = 0; j < 4; j++) {
            int cg = n0 + tx * 4 + j;
            if (cg < N) C[(size_t)rg * N + cg] = acc[i][j];
        }
    }
}

__global__ void adjmul_kernel(const float* __restrict__ adj, const float* __restrict__ X,
                              const float* __restrict__ bias, float* __restrict__ Y,
                              int F, int relu) {
    int total = BS * NNODE * F;
    for (int idx = blockIdx.x * blockDim.x + threadIdx.x; idx < total;
         idx += gridDim.x * blockDim.x) {
        int f = idx % F;
        int n = (idx / F) % NNODE;
        int b = idx / (F * NNODE);
        const float* Xb = X + (size_t)(b * NNODE) * F;
        const float* ad = adj + (size_t)(b * NNODE + n) * NNODE;
        float acc = bias[f];
#pragma unroll
        for (int m = 0; m < NNODE; m++)
            acc = fmaf(ad[m], Xb[(size_t)m * F + f], acc);
        if (relu) acc = fmaxf(acc, 0.f);
        Y[idx] = acc;
    }
}

// ---------------- host ----------------
extern "C" void kernel_launch(void* const* d_in, const int* in_sizes, int n_in,
                              void* d_out, int out_size) {
    const int*   inds = (const int*)  d_in[0];
    const int*   lens = (const int*)  d_in[1];
    const float* emb  = (const float*)d_in[2];
    const float* w_ih = (const float*)d_in[3];
    const float* w_hh = (const float*)d_in[4];
    const float* b_ih = (const float*)d_in[5];
    const float* b_hh = (const float*)d_in[6];
    const float* sg_x = (const float*)d_in[7];
    const float* adj  = (const float*)d_in[8];
    const float* gw1  = (const float*)d_in[9];
    const float* gb1  = (const float*)d_in[10];
    const float* gw2  = (const float*)d_in[11];
    const float* gb2  = (const float*)d_in[12];
    float* out = (float*)d_out;

    cudaFuncSetAttribute(gru_mma_kernel,
                         cudaFuncAttributeMaxDynamicSharedMemorySize, GRU_SMEM_BYTES);

    cudaMemsetAsync(d_out, 0, (size_t)out_size * sizeof(float), 0);
    zero_h_kernel<<<(B3 * HDIM + 511) / 512, 512>>>();
    prep_kernel<<<1, 256>>>(lens);
    transpose_wih_kernel<<<512, 256>>>(w_ih);

    xi_gemm_kernel<<<dim3(G3 / XBN, (B3 * SLEN) / XBM), 256>>>(inds, emb, b_ih);

    msks_kernel<<<BS, TT>>>(out);
    pack_emb_kernel<<<dim3(SLEN, B3), 64>>>(inds, emb, out);

    gru_mma_kernel<<<dim3(NKG, NBG), 256, GRU_SMEM_BYTES>>>(w_hh, b_hh, out);

    // GCN
    gemm64_kernel<<<dim3((NHID + 63) / 64, (BN + 63) / 64), 256>>>(sg_x, gw1, g_t1, BN, NHID, NFEAT);
    adjmul_kernel<<<1350, 512>>>(adj, g_t1, gb1, g_h1, NHID, 1);
    gemm64_kernel<<<dim3((NOUT + 63) / 64, (BN + 63) / 64), 256>>>(g_h1, gw2, g_t2, BN, NOUT, NHID);
    adjmul_kernel<<<2304, 512>>>(adj, g_t2, gb2, out + OUT_SG, NOUT, 0);
}

// round 9
// speedup vs baseline: 1.7369x; 1.3208x over previous
#include <cuda_runtime.h>
#include <math.h>
#include <stdint.h>

// ---------------- problem constants ----------------
#define BS    64
#define NSEG  3
#define SLEN  256
#define B3    192
#define TT    768
#define EDIM  300
#define HDIM  512
#define G3    1536
#define NNODE 18
#define NFEAT 600
#define NHID  600
#define NOUT  1024
#define BN    1152

// persistent GRU geometry
#define NKG   16
#define NBG   9
#define NSLOT 24

// output layout (floats)
#define OUT_RFTS 0UL
#define OUT_EMBS 25165824UL
#define OUT_MSKS 39911424UL
#define OUT_SG   39960576UL
#define OUT_HIDS 41140224UL

// GRU smem layout (floats)
#define WPK_FLOATS 49152
#define A_STRIDE   68
#define A0_OFF     WPK_FLOATS
#define A1_OFF     (A0_OFF + 32*A_STRIDE)
#define GHS_OFF    (A1_OFF + 32*A_STRIDE)
#define GHS_STRIDE 100
#define BSH_OFF    (GHS_OFF + 32*GHS_STRIDE)
#define SMEM_FLOATS (BSH_OFF + 96)
#define GRU_SMEM_BYTES (SMEM_FLOATS * 4)   // 227200 B

// ---------------- scratch ----------------
__device__ float g_xi[(size_t)B3 * SLEN * G3];
__device__ float g_h[2][B3 * HDIM];
__device__ float g_wihT[EDIM * G3];
__device__ float g_t1[BN * NHID];
__device__ float g_h1[BN * NHID];
__device__ float g_t2[BN * NOUT];
__device__ int   g_len[B3];
__device__ int   g_off[B3];
__device__ int   g_tlen[BS];
__device__ int   g_gmax[NBG];
__device__ int   g_bar_cnt[NBG];
__device__ int   g_bar_gen[NBG];
__device__ int   g_bmap[NBG * NSLOT];

// ---------------- helpers ----------------
__device__ __forceinline__ uint32_t tf32c(float x) {
    uint32_t u; asm("cvt.rna.tf32.f32 %0, %1;" : "=r"(u) : "f"(x)); return u;
}
__device__ __forceinline__ void mma8(float* d, uint32_t a0, uint32_t a1,
                                     uint32_t a2, uint32_t a3,
                                     uint32_t b0, uint32_t b1) {
    asm volatile(
        "mma.sync.aligned.m16n8k8.row.col.f32.tf32.tf32.f32 "
        "{%0,%1,%2,%3}, {%4,%5,%6,%7}, {%8,%9}, {%0,%1,%2,%3};"
        : "+f"(d[0]), "+f"(d[1]), "+f"(d[2]), "+f"(d[3])
        : "r"(a0), "r"(a1), "r"(a2), "r"(a3), "r"(b0), "r"(b1));
}

// ---------------- prep ----------------
__global__ void prep_kernel(const int* __restrict__ lens) {
    __shared__ int s_len[B3];
    __shared__ int hist[257];
    __shared__ int sorted_b[B3];
    int tid = threadIdx.x;

    for (int i = tid; i < 257; i += 256) hist[i] = 0;
    for (int i = tid; i < NBG * NSLOT; i += 256) g_bmap[i] = -1;
    if (tid < NBG) { g_bar_cnt[tid] = 0; g_bar_gen[tid] = 0; g_gmax[tid] = 0; }
    __syncthreads();

    if (tid < B3) {
        int l = lens[tid];
        s_len[tid] = l;
        g_len[tid] = l;
        atomicAdd(&hist[l], 1);
        int bb = tid / NSEG, s = tid % NSEG;
        int off = 0;
        for (int s2 = 0; s2 < s; s2++) off += lens[bb * NSEG + s2];
        g_off[tid] = off;
        if (s == 0)
            g_tlen[bb] = lens[bb*NSEG] + lens[bb*NSEG+1] + lens[bb*NSEG+2];
    }
    __syncthreads();
    if (tid == 0) {
        int acc = 0;
        for (int v = 1; v <= 256; v++) { int c = hist[v]; hist[v] = acc; acc += c; }
    }
    __syncthreads();
    if (tid < B3) {
        int pos = atomicAdd(&hist[s_len[tid]], 1);
        sorted_b[B3 - 1 - pos] = tid;
    }
    __syncthreads();
    if (tid < B3) {
        int i = tid;
        int b = sorted_b[i];
        int p = i % (2 * NBG);
        int g = (p < NBG) ? p : (2 * NBG - 1 - p);
        int slot = 2 * (i / (2 * NBG)) + ((p >= NBG) ? 1 : 0);
        g_bmap[g * NSLOT + slot] = b;
        atomicMax(&g_gmax[g], s_len[b]);
    }
    __syncthreads();
    // sort each group's slots descending by length (so slot16 bounds half-1 activity)
    if (tid < NBG) {
        int* gm = &g_bmap[tid * NSLOT];
        for (int i = 1; i < NSLOT; i++) {
            int b = gm[i];
            int l = (b >= 0) ? s_len[b] : -1;
            int j = i - 1;
            while (j >= 0) {
                int bj = gm[j];
                int lj = (bj >= 0) ? s_len[bj] : -1;
                if (lj < l) { gm[j + 1] = bj; j--; } else break;
            }
            gm[j + 1] = b;
        }
    }
}

__global__ void zero_h_kernel() {
    int i = blockIdx.x * blockDim.x + threadIdx.x;
    if (i < B3 * HDIM) g_h[0][i] = 0.f;
}

__global__ void transpose_wih_kernel(const float* __restrict__ w_ih) {
    for (int idx = blockIdx.x * blockDim.x + threadIdx.x;
         idx < EDIM * G3; idx += gridDim.x * blockDim.x) {
        int e = idx / G3, g = idx % G3;
        g_wihT[idx] = w_ih[g * EDIM + e];
    }
}

// ---------------- xi GEMM: tf32 mma.sync, 64x128 tile ----------------
#define YBM 64
#define YBN 128
#define ASTR 36
#define BSTR 132
#define NCH  10   // 10 chunks of 32 e (zero-padded past 300)

__global__ __launch_bounds__(256, 2)
void xi_mma_kernel(const int* __restrict__ inds, const float* __restrict__ emb,
                   const float* __restrict__ b_ih) {
    int tr = blockIdx.y * YBM;
    int n0 = blockIdx.x * YBN;
    int b3 = tr >> 8;
    int t0 = tr & 255;
    if (t0 >= g_len[b3]) return;

    __shared__ uint32_t As[YBM * ASTR];
    __shared__ uint32_t Bs[32 * BSTR];
    __shared__ int toksh[YBM];

    const int tid = threadIdx.x, lane = tid & 31, wid = tid >> 5;
    const int mi = wid & 3, nj = wid >> 2;

    if (tid < YBM) toksh[tid] = inds[tr + tid];
    __syncthreads();

    float d[8][4];
#pragma unroll
    for (int nt = 0; nt < 8; nt++)
#pragma unroll
        for (int j = 0; j < 4; j++) d[nt][j] = 0.f;

    const int arow = tid >> 2;            // 0..63
    const int aec  = (tid & 3) * 8;       // 0,8,16,24
    const int bes  = tid >> 3;            // 0..31
    const int bn4  = (tid & 7) * 16;

    for (int ch = 0; ch < NCH; ch++) {
        int e0 = ch * 32;
        // stage A: 64 rows x 32 e (gathered, tf32)
        {
            const float* ep = emb + (size_t)toksh[arow] * EDIM;
#pragma unroll
            for (int i = 0; i < 2; i++) {
                int e = e0 + aec + 4 * i;
                float4 v = make_float4(0.f, 0.f, 0.f, 0.f);
                if (e + 3 < EDIM) v = *(const float4*)(ep + e);
                else {
                    if (e     < EDIM) v.x = ep[e];
                    if (e + 1 < EDIM) v.y = ep[e + 1];
                    if (e + 2 < EDIM) v.z = ep[e + 2];
                    if (e + 3 < EDIM) v.w = ep[e + 3];
                }
                uint4 u;
                u.x = tf32c(v.x); u.y = tf32c(v.y); u.z = tf32c(v.z); u.w = tf32c(v.w);
                *(uint4*)&As[arow * ASTR + aec + 4 * i] = u;
            }
        }
        // stage B: 32 e x 128 n
        {
            bool ev = (e0 + bes) < EDIM;
            const float* bp = g_wihT + (size_t)(e0 + bes) * G3 + n0 + bn4;
#pragma unroll
            for (int i = 0; i < 4; i++) {
                float4 v = ev ? *(const float4*)(bp + 4 * i)
                              : make_float4(0.f, 0.f, 0.f, 0.f);
                uint4 u;
                u.x = tf32c(v.x); u.y = tf32c(v.y); u.z = tf32c(v.z); u.w = tf32c(v.w);
                *(uint4*)&Bs[bes * BSTR + bn4 + 4 * i] = u;
            }
        }
        __syncthreads();
#pragma unroll
        for (int ks = 0; ks < 4; ks++) {
            const uint32_t* ab = As + (16 * mi + (lane >> 2)) * ASTR + ks * 8 + (lane & 3);
            uint32_t a0 = ab[0];
            uint32_t a1 = ab[8 * ASTR];
            uint32_t a2 = ab[4];
            uint32_t a3 = ab[8 * ASTR + 4];
            const uint32_t* bb = Bs + (ks * 8 + (lane & 3)) * BSTR + nj * 64 + (lane >> 2);
#pragma unroll
            for (int nt = 0; nt < 8; nt++) {
                uint32_t b0 = bb[nt * 8];
                uint32_t b1 = bb[4 * BSTR + nt * 8];
                mma8(d[nt], a0, a1, a2, a3, b0, b1);
            }
        }
        __syncthreads();
    }
    // epilogue
    const int r0 = tr + 16 * mi + (lane >> 2);
    const int r1 = r0 + 8;
#pragma unroll
    for (int nt = 0; nt < 8; nt++) {
        int cg = n0 + nj * 64 + nt * 8 + 2 * (lane & 3);
        float2 bias = *(const float2*)&b_ih[cg];
        float2 v0 = make_float2(d[nt][0] + bias.x, d[nt][1] + bias.y);
        float2 v1 = make_float2(d[nt][2] + bias.x, d[nt][3] + bias.y);
        *(float2*)&g_xi[(size_t)r0 * G3 + cg] = v0;
        *(float2*)&g_xi[(size_t)r1 * G3 + cg] = v1;
    }
}

// ---------------- persistent GRU: tf32 mma, double-buffered staging ----------------
__global__ __launch_bounds__(256, 1)
void gru_mma_kernel(const float* __restrict__ w_hh, const float* __restrict__ b_hh,
                    float* __restrict__ out) {
    extern __shared__ float S[];
    uint32_t* Wu  = (uint32_t*)S;
    uint32_t* Au0 = (uint32_t*)(S + A0_OFF);
    uint32_t* Au1 = (uint32_t*)(S + A1_OFF);
    float*    ghs = S + GHS_OFF;
    float*    bsh = S + BSH_OFF;
    __shared__ int sb3[32];
    __shared__ int slen[32];
    __shared__ int srow[32];

    const int kg = blockIdx.x, bg = blockIdx.y;
    const int tid = threadIdx.x, lane = tid & 31, wid = tid >> 5;
    const int mi = wid & 1, nj = wid >> 1;

    if (tid < 32) {
        int b = (tid < NSLOT) ? g_bmap[bg * NSLOT + tid] : -1;
        sb3[tid] = b;
        slen[tid] = (b >= 0) ? g_len[b] : 0;
        srow[tid] = (b >= 0) ? ((b / NSEG) * TT + g_off[b]) : 0;
    }
    if (tid < 96) {
        int kc = tid / 3, g = tid - 3 * (tid / 3);
        bsh[tid] = b_hh[g * HDIM + kg * 32 + kc];
    }
    // W pack (B-fragment order) — verified in R7
    for (int i = tid; i < WPK_FLOATS; i += 256) {
        int p = i >> 1, half = i & 1;
        int l  = p & 31;
        int tq = p >> 5;
        int t  = tq % 3;
        int qn = tq / 3;
        int q  = qn & 63;
        int njj = qn >> 6;
        int e  = 8 * q + (l & 3) + 4 * half;
        int c  = 8 * t + (l >> 2);
        int kc = 8 * njj + c / 3;
        int g  = c - 3 * (c / 3);
        float v = w_hh[(size_t)(g * HDIM + kg * 32 + kc) * HDIM + e];
        Wu[i] = tf32c(v);
    }
    __syncthreads();

    const int gmax = g_gmax[bg];
    const int hmax1 = slen[16];           // sorted desc: bound for rows 16..31
    const int srowS = tid >> 3;
    const int soct  = tid & 7;
    const int g4 = lane >> 2, tg = lane & 3;

    const int sbb = sb3[srowS];
    const bool sval = (sbb >= 0);

    // per-item epilogue state carried in registers
    int   e_s[4], e_kc[4], e_b3[4], e_len[4], e_row[4];
    float hold[4];
#pragma unroll
    for (int it = 0; it < 4; it++) {
        int item = tid + it * 256;
        e_s[it] = item >> 5; e_kc[it] = item & 31;
        e_b3[it] = sb3[e_s[it]];
        e_len[it] = slen[e_s[it]];
        e_row[it] = srow[e_s[it]];
        hold[it] = 0.f;
    }

    for (int t = 0; t < gmax; t++) {
        const float* __restrict__ hc = g_h[t & 1];
        float* __restrict__ hn = g_h[(t + 1) & 1];
        const bool act = (mi == 0) || (t < hmax1);

        const float* hrow = sval ? (hc + (size_t)sbb * HDIM) : hc;

        // prefetch h chunk 0
        float4 pv0, pv1;
        if (sval) {
            const float4* hp = (const float4*)(hrow + soct * 8);
            pv0 = hp[0]; pv1 = hp[1];
        } else { pv0 = pv1 = make_float4(0.f,0.f,0.f,0.f); }

        // prefetch epilogue xi (overlaps with MMA phase)
        float xiv[4][3];
#pragma unroll
        for (int it = 0; it < 4; it++) {
            xiv[it][0] = xiv[it][1] = xiv[it][2] = 0.f;
            if (e_b3[it] >= 0 && t < e_len[it]) {
                const float* xp = g_xi + ((size_t)e_b3[it] * SLEN + t) * G3 + kg * 32 + e_kc[it];
                xiv[it][0] = xp[0];
                xiv[it][1] = xp[HDIM];
                xiv[it][2] = xp[2 * HDIM];
            }
        }

        // stage chunk 0 -> buf0
        {
            uint4 u0, u1;
            u0.x = tf32c(pv0.x); u0.y = tf32c(pv0.y); u0.z = tf32c(pv0.z); u0.w = tf32c(pv0.w);
            u1.x = tf32c(pv1.x); u1.y = tf32c(pv1.y); u1.z = tf32c(pv1.z); u1.w = tf32c(pv1.w);
            uint32_t* ap = Au0 + srowS * A_STRIDE + soct * 8;
            *(uint4*)ap = u0;
            *(uint4*)(ap + 4) = u1;
        }
        __syncthreads();

        float d0[4] = {0,0,0,0}, d1[4] = {0,0,0,0}, d2[4] = {0,0,0,0};

#pragma unroll
        for (int ch = 0; ch < 8; ch++) {
            if (ch < 7 && sval) {
                const float4* hp = (const float4*)(hrow + (ch + 1) * 64 + soct * 8);
                pv0 = hp[0]; pv1 = hp[1];
            }
            if (act) {
                const uint32_t* Abuf = (ch & 1) ? Au1 : Au0;
#pragma unroll
                for (int ql = 0; ql < 8; ql++) {
                    const uint32_t* ab = Abuf + (16 * mi + g4) * A_STRIDE + ql * 8 + tg;
                    uint32_t a0 = ab[0];
                    uint32_t a1 = ab[8 * A_STRIDE];
                    uint32_t a2 = ab[4];
                    uint32_t a3 = ab[8 * A_STRIDE + 4];
                    int q = ch * 8 + ql;
                    const uint2* wp = (const uint2*)Wu + ((nj * 64 + q) * 3) * 32 + lane;
                    uint2 bf0 = wp[0];
                    uint2 bf1 = wp[32];
                    uint2 bf2 = wp[64];
                    mma8(d0, a0, a1, a2, a3, bf0.x, bf0.y);
                    mma8(d1, a0, a1, a2, a3, bf1.x, bf1.y);
                    mma8(d2, a0, a1, a2, a3, bf2.x, bf2.y);
                }
            }
            if (ch < 7) {
                uint4 u0, u1;
                u0.x = tf32c(pv0.x); u0.y = tf32c(pv0.y); u0.z = tf32c(pv0.z); u0.w = tf32c(pv0.w);
                u1.x = tf32c(pv1.x); u1.y = tf32c(pv1.y); u1.z = tf32c(pv1.z); u1.w = tf32c(pv1.w);
                uint32_t* Adst = ((ch + 1) & 1) ? Au1 : Au0;
                uint32_t* ap = Adst + srowS * A_STRIDE + soct * 8;
                *(uint4*)ap = u0;
                *(uint4*)(ap + 4) = u1;
            }
            __syncthreads();
        }

        if (act) {
            int r0 = (16 * mi + g4) * GHS_STRIDE;
            int r1 = (16 * mi + 8 + g4) * GHS_STRIDE;
            int nb = 24 * nj + 2 * tg;
            ghs[r0 + nb]      = d0[0]; ghs[r0 + nb + 1]  = d0[1];
            ghs[r1 + nb]      = d0[2]; ghs[r1 + nb + 1]  = d0[3];
            ghs[r0 + nb + 8]  = d1[0]; ghs[r0 + nb + 9]  = d1[1];
            ghs[r1 + nb + 8]  = d1[2]; ghs[r1 + nb + 9]  = d1[3];
            ghs[r0 + nb + 16] = d2[0]; ghs[r0 + nb + 17] = d2[1];
            ghs[r1 + nb + 16] = d2[2]; ghs[r1 + nb + 17] = d2[3];
        }
        __syncthreads();

        // epilogue
#pragma unroll
        for (int it = 0; it < 4; it++) {
            int b3 = e_b3[it];
            if (b3 < 0) continue;
            int kglob = kg * 32 + e_kc[it];
            float hv = hold[it];
            if (t < e_len[it]) {
                int s = e_s[it], kc = e_kc[it];
                float gr = ghs[s * GHS_STRIDE + 3 * kc + 0];
                float gz = ghs[s * GHS_STRIDE + 3 * kc + 1];
                float gn = ghs[s * GHS_STRIDE + 3 * kc + 2];
                float rr = 1.f / (1.f + expf(-(xiv[it][0] + gr + bsh[3 * kc])));
                float zz = 1.f / (1.f + expf(-(xiv[it][1] + gz + bsh[3 * kc + 1])));
                float nn = tanhf(xiv[it][2] + rr * (gn + bsh[3 * kc + 2]));
                hv = (1.f - zz) * nn + zz * hold[it];
                out[OUT_RFTS + (size_t)(e_row[it] + t) * HDIM + kglob] = hv;
            }
            hold[it] = hv;
            hn[(size_t)b3 * HDIM + kglob] = hv;
        }

        // inter-CTA barrier (volatile poll)
        __threadfence();
        __syncthreads();
        if (tid == 0) {
            int a = atomicAdd(&g_bar_cnt[bg], 1);
            if (a == NKG - 1) {
                atomicExch(&g_bar_cnt[bg], 0);
                __threadfence();
                atomicExch(&g_bar_gen[bg], t + 1);
            } else {
                const volatile int* gv = (const volatile int*)&g_bar_gen[bg];
                while (*gv <= t) { }
                __threadfence();
            }
        }
        __syncthreads();
    }

    // final hidden states from carried registers
#pragma unroll
    for (int it = 0; it < 4; it++) {
        if (e_b3[it] >= 0)
            out[OUT_HIDS + (size_t)e_b3[it] * HDIM + kg * 32 + e_kc[it]] = hold[it];
    }
}

// ---------------- packing & masks ----------------
__global__ void msks_kernel(float* __restrict__ out) {
    int b = blockIdx.x, t = threadIdx.x;
    out[OUT_MSKS + (size_t)b * TT + t] = (t < g_tlen[b]) ? 1.f : 0.f;
}

__global__ void pack_emb_kernel(const int* __restrict__ inds,
                                const float* __restrict__ emb,
                                float* __restrict__ out) {
    int t = blockIdx.x, b3 = blockIdx.y;
    if (t >= g_len[b3]) return;
    int tok = inds[b3 * SLEN + t];
    size_t row = (size_t)(b3 / 3) * TT + g_off[b3] + t;
    for (int e = threadIdx.x; e < EDIM; e += blockDim.x)
        out[OUT_EMBS + row * EDIM + e] = emb[(size_t)tok * EDIM + e];
}

// ---------------- GCN GEMM ----------------
__global__ __launch_bounds__(256)
void gemm64_kernel(const float* __restrict__ A, const float* __restrict__ B,
                   float* __restrict__ C, int M, int N, int K) {
    const int BK = 8;
    int m0 = blockIdx.y * 64, n0 = blockIdx.x * 64;
    __shared__ float As[BK * 64];
    __shared__ float Bs[BK * 64];
    int tid = threadIdx.x;
    int tx = tid & 15, ty = tid >> 4;

    float acc[4][4];
#pragma unroll
    for (int i = 0; i < 4; i++)
#pragma unroll
        for (int j = 0; j < 4; j++) acc[i][j] = 0.f;

    for (int k0 = 0; k0 < K; k0 += BK) {
#pragma unroll
        for (int i = 0; i < 2; i++) {
            int idx = tid + i * 256;
            int r = idx / BK, e = idx % BK;
            float v = 0.f;
            if (m0 + r < M) v = A[(size_t)(m0 + r) * K + k0 + e];
            As[e * 64 + r] = v;
        }
#pragma unroll
        for (int i = 0; i < 2; i++) {
            int idx = tid + i * 256;
            int e = idx >> 6, n = idx & 63;
            float v = 0.f;
            if (n0 + n < N) v = B[(size_t)(k0 + e) * N + n0 + n];
            Bs[e * 64 + n] = v;
        }
        __syncthreads();
#pragma unroll
        for (int e = 0; e < BK; e++) {
            float4 a = *(const float4*)&As[e * 64 + ty * 4];
            float4 b = *(const float4*)&Bs[e * 64 + tx * 4];
            acc[0][0] = fmaf(a.x, b.x, acc[0][0]); acc[0][1] = fmaf(a.x, b.y, acc[0][1]);
            acc[0][2] = fmaf(a.x, b.z, acc[0][2]); acc[0][3] = fmaf(a.x, b.w, acc[0][3]);
            acc[1][0] = fmaf(a.y, b.x, acc[1][0]); acc[1][1] = fmaf(a.y, b.y, acc[1][1]);
            acc[1][2] = fmaf(a.y, b.z, acc[1][2]); acc[1][3] = fmaf(a.y, b.w, acc[1][3]);
            acc[2][0] = fmaf(a.z, b.x, acc[2][0]); acc[2][1] = fmaf(a.z, b.y, acc[2][1]);
            acc[2][2] = fmaf(a.z, b.z, acc[2][2]); acc[2][3] = fmaf(a.z, b.w, acc[2][3]);
            acc[3][0] = fmaf(a.w, b.x, acc[3][0]); acc[3][1] = fmaf(a.w, b.y, acc[3][1]);
            acc[3][2] = fmaf(a.w, b.z, acc[3][2]); acc[3][3] = fmaf(a.w, b.w, acc[3][3]);
        }
        __syncthreads();
    }
#pragma unroll
    for (int i = 0; i < 4; i++) {
        int rg = m0 + ty * 4 + i;
        if (rg >= M) continue;
#pragma unroll
        for (int j = 0; j < 4; j++) {
            int cg = n0 + tx * 4 + j;
            if (cg < N) C[(size_t)rg * N + cg] = acc[i][j];
        }
    }
}

__global__ void adjmul_kernel(const float* __restrict__ adj, const float* __restrict__ X,
                              const float* __restrict__ bias, float* __restrict__ Y,
                              int F, int relu) {
    int total = BS * NNODE * F;
    for (int idx = blockIdx.x * blockDim.x + threadIdx.x; idx < total;
         idx += gridDim.x * blockDim.x) {
        int f = idx % F;
        int n = (idx / F) % NNODE;
        int b = idx / (F * NNODE);
        const float* Xb = X + (size_t)(b * NNODE) * F;
        const float* ad = adj + (size_t)(b * NNODE + n) * NNODE;
        float acc = bias[f];
#pragma unroll
        for (int m = 0; m < NNODE; m++)
            acc = fmaf(ad[m], Xb[(size_t)m * F + f], acc);
        if (relu) acc = fmaxf(acc, 0.f);
        Y[idx] = acc;
    }
}

// ---------------- host ----------------
extern "C" void kernel_launch(void* const* d_in, const int* in_sizes, int n_in,
                              void* d_out, int out_size) {
    const int*   inds = (const int*)  d_in[0];
    const int*   lens = (const int*)  d_in[1];
    const float* emb  = (const float*)d_in[2];
    const float* w_ih = (const float*)d_in[3];
    const float* w_hh = (const float*)d_in[4];
    const float* b_ih = (const float*)d_in[5];
    const float* b_hh = (const float*)d_in[6];
    const float* sg_x = (const float*)d_in[7];
    const float* adj  = (const float*)d_in[8];
    const float* gw1  = (const float*)d_in[9];
    const float* gb1  = (const float*)d_in[10];
    const float* gw2  = (const float*)d_in[11];
    const float* gb2  = (const float*)d_in[12];
    float* out = (float*)d_out;

    cudaFuncSetAttribute(gru_mma_kernel,
                         cudaFuncAttributeMaxDynamicSharedMemorySize, GRU_SMEM_BYTES);

    cudaMemsetAsync(d_out, 0, (size_t)out_size * sizeof(float), 0);
    zero_h_kernel<<<(B3 * HDIM + 511) / 512, 512>>>();
    prep_kernel<<<1, 256>>>(lens);
    transpose_wih_kernel<<<512, 256>>>(w_ih);

    xi_mma_kernel<<<dim3(G3 / YBN, (B3 * SLEN) / YBM), 256>>>(inds, emb, b_ih);

    msks_kernel<<<BS, TT>>>(out);
    pack_emb_kernel<<<dim3(SLEN, B3), 64>>>(inds, emb, out);

    gru_mma_kernel<<<dim3(NKG, NBG), 256, GRU_SMEM_BYTES>>>(w_hh, b_hh, out);

    // GCN
    gemm64_kernel<<<dim3((NHID + 63) / 64, (BN + 63) / 64), 256>>>(sg_x, gw1, g_t1, BN, NHID, NFEAT);
    adjmul_kernel<<<1350, 512>>>(adj, g_t1, gb1, g_h1, NHID, 1);
    gemm64_kernel<<<dim3((NOUT + 63) / 64, (BN + 63) / 64), 256>>>(g_h1, gw2, g_t2, BN, NOUT, NHID);
    adjmul_kernel<<<2304, 512>>>(adj, g_t2, gb2, out + OUT_SG, NOUT, 0);
}